// round 15
// baseline (speedup 1.0000x reference)
#include <cuda_runtime.h>
#include <cuda_fp16.h>
#include <cstdint>

#define BSZ     4
#define SEQ     4096
#define DIM     4096
#define NHEADS  32
#define NKV     8
#define HD      128
#define NTOT    6144
#define MTOT    (BSZ*SEQ)            // 16384

#define TM      128
#define TN      128                  // one head per column tile
#define TK      64                   // 64 halves = 128B per row
#define NKT     (DIM/TK)             // 64
#define PITCH   144                  // bytes per smem row (64*2 + 16 pad): conflict-free
#define STAGES  3
#define THREADS 256

#define A_BYTES (TM*PITCH)           // 18432
#define B_BYTES (TN*PITCH)           // 18432
#define STAGE_BYTES (A_BYTES + B_BYTES)      // 36864
#define SMEM_BYTES (STAGES*STAGE_BYTES)      // 110592 -> 2 CTAs/SM (216KB of 228KB)

#define GSUP    8                    // m-tiles per supertile (L2 blocking)

// ---------------- scratch: fp16 copies ----------------
__device__ __half g_xh[(size_t)MTOT * DIM];  // 128 MB
__device__ __half g_wh[(size_t)NTOT * DIM];  //  48 MB

// ---------------- pre-pass: fp32 -> fp16(RN) ----------------
__global__ void __launch_bounds__(256) cvt_f16_kernel(const float4* __restrict__ in,
                                                      __half* __restrict__ out, int n4) {
    int i = blockIdx.x * blockDim.x + threadIdx.x;
    int stride = gridDim.x * blockDim.x;
    for (; i < n4; i += stride) {
        float4 v = __ldcs(in + i);
        __half2 h0 = __floats2half2_rn(v.x, v.y);
        __half2 h1 = __floats2half2_rn(v.z, v.w);
        uint2 o;
        o.x = *reinterpret_cast<uint32_t*>(&h0);
        o.y = *reinterpret_cast<uint32_t*>(&h1);
        __stcs(reinterpret_cast<uint2*>(out + (size_t)i * 4), o);
    }
}

// ---------------- main GEMM + RoPE ----------------
__global__ void __launch_bounds__(THREADS, 2)
qkv_hmma_f16_kernel(const __half* __restrict__ xh, const __half* __restrict__ wh,
                    const float* __restrict__ cosT, const float* __restrict__ sinT,
                    float* __restrict__ out)
{
    extern __shared__ char smem[];

    // supertile decode: 8 consecutive blocks = same head, 8 m-tiles
    const int id   = blockIdx.x;
    const int sg   = id / (48 * GSUP);
    const int rem  = id % (48 * GSUP);
    const int head = rem >> 3;                 // 0..47
    const int mt   = sg * GSUP + (rem & 7);    // 0..127
    const int m0   = mt * TM;
    const int n0   = head * TN;

    const int t    = threadIdx.x;
    const uint32_t sb = (uint32_t)__cvta_generic_to_shared(smem);

    auto stage = [&](int kt, int buf) {
        const __half* asrc = xh + (size_t)m0 * DIM + kt * TK;
        const __half* bsrc = wh + (size_t)n0 * DIM + kt * TK;
        uint32_t abase = sb + (uint32_t)(buf * STAGE_BYTES);
        uint32_t bbase = abase + A_BYTES;
        #pragma unroll
        for (int j = 0; j < 4; j++) {                  // A: 128 rows * 8 chunks / 256 thr
            int f = t + j * THREADS;
            int row = f >> 3, c = f & 7;
            uint32_t d = abase + (uint32_t)(row * PITCH + c * 16);
            const __half* s = asrc + (size_t)row * DIM + c * 8;
            asm volatile("cp.async.cg.shared.global [%0], [%1], 16;\n" :: "r"(d), "l"(s));
        }
        #pragma unroll
        for (int j = 0; j < 4; j++) {                  // B: 128 rows * 8 chunks / 256 thr
            int f = t + j * THREADS;
            int row = f >> 3, c = f & 7;
            uint32_t d = bbase + (uint32_t)(row * PITCH + c * 16);
            const __half* s = bsrc + (size_t)row * DIM + c * 8;
            asm volatile("cp.async.cg.shared.global [%0], [%1], 16;\n" :: "r"(d), "l"(s));
        }
        asm volatile("cp.async.commit_group;\n");
    };

    const int lane = t & 31, wid = t >> 5;     // 8 warps
    const int wm = wid >> 2, wn = wid & 3;     // 2x4 grid of 64x32 warp tiles
    const int g  = lane >> 2, t4 = lane & 3;

    // ldmatrix lane addressing (both operands K-major -> plain ldmatrix, NO .trans)
    // A (x4): mats = {m0-7 k0-7, m8-15 k0-7, m0-7 k8-15, m8-15 k8-15}
    const int a_row  = wm * 64 + (lane & 15);
    const int a_koff = (lane >> 4) * 16;                 // bytes
    // B (x4): mats = {n0-7 k0-7, n0-7 k8-15, n8-15 k0-7, n8-15 k8-15}
    const int b_row  = wn * 32 + (lane & 7) + ((lane & 16) >> 1);
    const int b_koff = ((lane >> 3) & 1) * 16;           // bytes

    float acc[4][4][4];
    #pragma unroll
    for (int a = 0; a < 4; a++)
        #pragma unroll
        for (int b = 0; b < 4; b++)
            #pragma unroll
            for (int c = 0; c < 4; c++) acc[a][b][c] = 0.f;

    stage(0, 0);
    stage(1, 1);

    // 3-buffer, single-sync-per-iteration pipeline:
    //  top barrier of iteration kt proves all warps finished compute(kt-1)
    //  (which read buf (kt+2)%3), so stage(kt+2) can safely overwrite it.
    int buf = 0;
    for (int kt = 0; kt < NKT; kt++) {
        if (kt < NKT - 1) { asm volatile("cp.async.wait_group 1;\n"); }
        else              { asm volatile("cp.async.wait_group 0;\n"); }
        __syncthreads();
        if (kt + 2 < NKT) stage(kt + 2, (kt + 2) % STAGES);

        const uint32_t sA = sb + (uint32_t)(buf * STAGE_BYTES);
        const uint32_t sB = sA + A_BYTES;
        const uint32_t aab = sA + (uint32_t)(a_row * PITCH + a_koff);
        const uint32_t bab = sB + (uint32_t)(b_row * PITCH + b_koff);

        #pragma unroll
        for (int kk = 0; kk < 4; kk++) {               // 4 x k16 per stage
            uint32_t af[4][4], bf[2][4];
            #pragma unroll
            for (int mi = 0; mi < 4; mi++)
                asm volatile("ldmatrix.sync.aligned.m8n8.x4.shared.b16 {%0,%1,%2,%3}, [%4];"
                             : "=r"(af[mi][0]), "=r"(af[mi][1]), "=r"(af[mi][2]), "=r"(af[mi][3])
                             : "r"(aab + (uint32_t)(mi * 16 * PITCH + kk * 32)));
            #pragma unroll
            for (int bi = 0; bi < 2; bi++)
                asm volatile("ldmatrix.sync.aligned.m8n8.x4.shared.b16 {%0,%1,%2,%3}, [%4];"
                             : "=r"(bf[bi][0]), "=r"(bf[bi][1]), "=r"(bf[bi][2]), "=r"(bf[bi][3])
                             : "r"(bab + (uint32_t)(bi * 16 * PITCH + kk * 32)));
            #pragma unroll
            for (int mi = 0; mi < 4; mi++)
                #pragma unroll
                for (int ni = 0; ni < 4; ni++)
                    asm volatile(
                        "mma.sync.aligned.m16n8k16.row.col.f32.f16.f16.f32 "
                        "{%0,%1,%2,%3}, {%4,%5,%6,%7}, {%8,%9}, {%0,%1,%2,%3};\n"
                        : "+f"(acc[mi][ni][0]), "+f"(acc[mi][ni][1]),
                          "+f"(acc[mi][ni][2]), "+f"(acc[mi][ni][3])
                        : "r"(af[mi][0]), "r"(af[mi][1]), "r"(af[mi][2]), "r"(af[mi][3]),
                          "r"(bf[ni >> 1][(ni & 1) * 2]), "r"(bf[ni >> 1][(ni & 1) * 2 + 1]));
        }
        buf = (buf + 1 == STAGES) ? 0 : buf + 1;
    }

    // ---------------- epilogue: RoPE + (b, h, s, d) scatter ----------------
    const size_t QSZ = (size_t)BSZ * NHEADS * SEQ * HD;   // 67108864
    const size_t KSZ = (size_t)BSZ * NKV    * SEQ * HD;   // 16777216
    size_t obase; int h, nh;
    if (head < NHEADS)            { obase = 0;         h = head;                nh = NHEADS; }
    else if (head < NHEADS + NKV) { obase = QSZ;       h = head - NHEADS;       nh = NKV; }
    else                          { obase = QSZ + KSZ; h = head - NHEADS - NKV; nh = NKV; }
    const bool rope  = head < NHEADS + NKV;
    const int  bb    = m0 >> 12;          // 128-row tile never straddles a batch
    const int  sbase = m0 & (SEQ - 1);
    float* ob = out + obase + ((size_t)bb * nh + h) * (size_t)SEQ * HD;

    #pragma unroll
    for (int mi = 0; mi < 4; mi++) {
        #pragma unroll
        for (int ni = 0; ni < 4; ni++) {
            const int d = wn * 32 + ni * 8 + t4 * 2;   // even: RoPE pair (d, d+1) in-thread
            const int i = d >> 1;
            #pragma unroll
            for (int hl = 0; hl < 2; hl++) {
                const int s = sbase + wm * 64 + mi * 16 + g + hl * 8;
                float v0 = acc[mi][ni][hl * 2 + 0];
                float v1 = acc[mi][ni][hl * 2 + 1];
                if (rope) {
                    const float cs = __ldg(cosT + (size_t)s * 64 + i);
                    const float sn = __ldg(sinT + (size_t)s * 64 + i);
                    const float r0 = v0 * cs - v1 * sn;
                    const float r1 = v0 * sn + v1 * cs;
                    v0 = r0; v1 = r1;
                }
                float2 vv; vv.x = v0; vv.y = v1;
                __stcs(reinterpret_cast<float2*>(ob + (size_t)s * HD + d), vv);
            }
        }
    }
}

// ---------------- host ----------------
extern "C" void kernel_launch(void* const* d_in, const int* in_sizes, int n_in,
                              void* d_out, int out_size)
{
    const float* x    = (const float*)d_in[0];
    const float* wq   = (const float*)d_in[1];
    const float* wk   = (const float*)d_in[2];
    const float* wv   = (const float*)d_in[3];
    const float* cosT = (const float*)d_in[4];
    const float* sinT = (const float*)d_in[5];
    float* out = (float*)d_out;

    void *xh = nullptr, *wh = nullptr;
    cudaGetSymbolAddress(&xh, g_xh);
    cudaGetSymbolAddress(&wh, g_wh);

    // pre-pass: round-to-nearest fp16 copies
    cvt_f16_kernel<<<4096, 256>>>((const float4*)x, (__half*)xh, MTOT * DIM / 4);
    cvt_f16_kernel<<<2048, 256>>>((const float4*)wq, (__half*)wh, NHEADS * HD * DIM / 4);
    cvt_f16_kernel<<<1024, 256>>>((const float4*)wk,
        (__half*)wh + (size_t)NHEADS * HD * DIM, NKV * HD * DIM / 4);
    cvt_f16_kernel<<<1024, 256>>>((const float4*)wv,
        (__half*)wh + (size_t)(NHEADS + NKV) * HD * DIM, NKV * HD * DIM / 4);

    cudaFuncSetAttribute(qkv_hmma_f16_kernel,
                         cudaFuncAttributeMaxDynamicSharedMemorySize, SMEM_BYTES);

    const int grid = (MTOT / TM) * (NTOT / TN);   // 128 * 48 = 6144
    qkv_hmma_f16_kernel<<<grid, THREADS, SMEM_BYTES>>>(
        (const __half*)xh, (const __half*)wh, cosT, sinT, out);
}

// round 16
// speedup vs baseline: 1.0696x; 1.0696x over previous
#include <cuda_runtime.h>
#include <cuda_fp16.h>
#include <cstdint>

#define BSZ     4
#define SEQ     4096
#define DIM     4096
#define NHEADS  32
#define NKV     8
#define HD      128
#define NTOT    6144
#define MTOT    (BSZ*SEQ)            // 16384

#define TM      128
#define TN      128                  // one head per column tile
#define TK      64                   // 64 halves = 128B per row
#define NKT     (DIM/TK)             // 64
#define PITCH   144                  // bytes per smem row (64*2 + 16 pad): conflict-free
#define STAGES  2
#define THREADS 256

#define A_BYTES (TM*PITCH)           // 18432
#define B_BYTES (TN*PITCH)           // 18432
#define STAGE_BYTES (A_BYTES + B_BYTES)      // 36864
#define SMEM_BYTES (STAGES*STAGE_BYTES)      // 73728  -> 2 CTAs/SM

#define GSUP    8                    // m-tiles per supertile (L2 blocking)

// ---------------- scratch: fp16 copies ----------------
__device__ __half g_xh[(size_t)MTOT * DIM];  // 128 MB
__device__ __half g_wh[(size_t)NTOT * DIM];  //  48 MB

// ---------------- pre-pass: fp32 -> fp16(RN), MLP-4 streaming ----------------
// Each thread: 4 independent LDG.128 (2 pairs), 2 STG.128 (8 halves each).
// Grid must exactly cover n4 (n4 % 1024 == 0 for all our tensors).
__global__ void __launch_bounds__(256) cvt_f16_kernel(const uint4* __restrict__ in,
                                                      uint4* __restrict__ out) {
    const int    tid  = threadIdx.x;
    const size_t base = (size_t)blockIdx.x * 1024;   // float4 units per block: 256thr*4

    #pragma unroll
    for (int j = 0; j < 2; j++) {
        const size_t i4 = base + (size_t)j * 512 + (size_t)tid * 2;  // consecutive pair
        uint4 a = __ldcs(in + i4);
        uint4 b = __ldcs(in + i4 + 1);
        const float4 fa = *reinterpret_cast<const float4*>(&a);
        const float4 fb = *reinterpret_cast<const float4*>(&b);
        __half2 h0 = __floats2half2_rn(fa.x, fa.y);
        __half2 h1 = __floats2half2_rn(fa.z, fa.w);
        __half2 h2 = __floats2half2_rn(fb.x, fb.y);
        __half2 h3 = __floats2half2_rn(fb.z, fb.w);
        uint4 o;
        o.x = *reinterpret_cast<uint32_t*>(&h0);
        o.y = *reinterpret_cast<uint32_t*>(&h1);
        o.z = *reinterpret_cast<uint32_t*>(&h2);
        o.w = *reinterpret_cast<uint32_t*>(&h3);
        __stcs(out + i4 / 2, o);
    }
}

// ---------------- main GEMM + RoPE (exact R14 structure) ----------------
__global__ void __launch_bounds__(THREADS, 2)
qkv_hmma_f16_kernel(const __half* __restrict__ xh, const __half* __restrict__ wh,
                    const float* __restrict__ cosT, const float* __restrict__ sinT,
                    float* __restrict__ out)
{
    extern __shared__ char smem[];

    // supertile decode: 8 consecutive blocks = same head, 8 m-tiles
    const int id   = blockIdx.x;
    const int sg   = id / (48 * GSUP);
    const int rem  = id % (48 * GSUP);
    const int head = rem >> 3;                 // 0..47
    const int mt   = sg * GSUP + (rem & 7);    // 0..127
    const int m0   = mt * TM;
    const int n0   = head * TN;

    const int t    = threadIdx.x;
    const uint32_t sb = (uint32_t)__cvta_generic_to_shared(smem);

    auto stage = [&](int kt, int buf) {
        const __half* asrc = xh + (size_t)m0 * DIM + kt * TK;
        const __half* bsrc = wh + (size_t)n0 * DIM + kt * TK;
        uint32_t abase = sb + (uint32_t)(buf * STAGE_BYTES);
        uint32_t bbase = abase + A_BYTES;
        #pragma unroll
        for (int j = 0; j < 4; j++) {                  // A: 128 rows * 8 chunks / 256 thr
            int f = t + j * THREADS;
            int row = f >> 3, c = f & 7;
            uint32_t d = abase + (uint32_t)(row * PITCH + c * 16);
            const __half* s = asrc + (size_t)row * DIM + c * 8;
            asm volatile("cp.async.cg.shared.global [%0], [%1], 16;\n" :: "r"(d), "l"(s));
        }
        #pragma unroll
        for (int j = 0; j < 4; j++) {                  // B: 128 rows * 8 chunks / 256 thr
            int f = t + j * THREADS;
            int row = f >> 3, c = f & 7;
            uint32_t d = bbase + (uint32_t)(row * PITCH + c * 16);
            const __half* s = bsrc + (size_t)row * DIM + c * 8;
            asm volatile("cp.async.cg.shared.global [%0], [%1], 16;\n" :: "r"(d), "l"(s));
        }
        asm volatile("cp.async.commit_group;\n");
    };

    const int lane = t & 31, wid = t >> 5;     // 8 warps
    const int wm = wid >> 2, wn = wid & 3;     // 2x4 grid of 64x32 warp tiles
    const int g  = lane >> 2, t4 = lane & 3;

    // ldmatrix lane addressing (both operands K-major -> plain ldmatrix, NO .trans)
    const int a_row  = wm * 64 + (lane & 15);
    const int a_koff = (lane >> 4) * 16;                 // bytes
    const int b_row  = wn * 32 + (lane & 7) + ((lane & 16) >> 1);
    const int b_koff = ((lane >> 3) & 1) * 16;           // bytes

    float acc[4][4][4];
    #pragma unroll
    for (int a = 0; a < 4; a++)
        #pragma unroll
        for (int b = 0; b < 4; b++)
            #pragma unroll
            for (int c = 0; c < 4; c++) acc[a][b][c] = 0.f;

    stage(0, 0);

    for (int kt = 0; kt < NKT; kt++) {
        asm volatile("cp.async.wait_group 0;\n");      // stage(kt) complete
        __syncthreads();                               // + all warps done with buf (kt+1)&1
        if (kt + 1 < NKT) stage(kt + 1, (kt + 1) & 1); // prefetch overlaps compute below

        const uint32_t sA = sb + (uint32_t)((kt & 1) * STAGE_BYTES);
        const uint32_t sB = sA + A_BYTES;
        const uint32_t aab = sA + (uint32_t)(a_row * PITCH + a_koff);
        const uint32_t bab = sB + (uint32_t)(b_row * PITCH + b_koff);

        #pragma unroll
        for (int kk = 0; kk < 4; kk++) {               // 4 x k16 per stage
            uint32_t af[4][4], bf[2][4];
            #pragma unroll
            for (int mi = 0; mi < 4; mi++)
                asm volatile("ldmatrix.sync.aligned.m8n8.x4.shared.b16 {%0,%1,%2,%3}, [%4];"
                             : "=r"(af[mi][0]), "=r"(af[mi][1]), "=r"(af[mi][2]), "=r"(af[mi][3])
                             : "r"(aab + (uint32_t)(mi * 16 * PITCH + kk * 32)));
            #pragma unroll
            for (int bi = 0; bi < 2; bi++)
                asm volatile("ldmatrix.sync.aligned.m8n8.x4.shared.b16 {%0,%1,%2,%3}, [%4];"
                             : "=r"(bf[bi][0]), "=r"(bf[bi][1]), "=r"(bf[bi][2]), "=r"(bf[bi][3])
                             : "r"(bab + (uint32_t)(bi * 16 * PITCH + kk * 32)));
            #pragma unroll
            for (int mi = 0; mi < 4; mi++)
                #pragma unroll
                for (int ni = 0; ni < 4; ni++)
                    asm volatile(
                        "mma.sync.aligned.m16n8k16.row.col.f32.f16.f16.f32 "
                        "{%0,%1,%2,%3}, {%4,%5,%6,%7}, {%8,%9}, {%0,%1,%2,%3};\n"
                        : "+f"(acc[mi][ni][0]), "+f"(acc[mi][ni][1]),
                          "+f"(acc[mi][ni][2]), "+f"(acc[mi][ni][3])
                        : "r"(af[mi][0]), "r"(af[mi][1]), "r"(af[mi][2]), "r"(af[mi][3]),
                          "r"(bf[ni >> 1][(ni & 1) * 2]), "r"(bf[ni >> 1][(ni & 1) * 2 + 1]));
        }
        __syncthreads();                               // protect buf kt&1 before next prefetch
    }

    // ---------------- epilogue: RoPE + (b, h, s, d) scatter ----------------
    const size_t QSZ = (size_t)BSZ * NHEADS * SEQ * HD;   // 67108864
    const size_t KSZ = (size_t)BSZ * NKV    * SEQ * HD;   // 16777216
    size_t obase; int h, nh;
    if (head < NHEADS)            { obase = 0;         h = head;                nh = NHEADS; }
    else if (head < NHEADS + NKV) { obase = QSZ;       h = head - NHEADS;       nh = NKV; }
    else                          { obase = QSZ + KSZ; h = head - NHEADS - NKV; nh = NKV; }
    const bool rope  = head < NHEADS + NKV;
    const int  bb    = m0 >> 12;          // 128-row tile never straddles a batch
    const int  sbase = m0 & (SEQ - 1);
    float* ob = out + obase + ((size_t)bb * nh + h) * (size_t)SEQ * HD;

    #pragma unroll
    for (int mi = 0; mi < 4; mi++) {
        #pragma unroll
        for (int ni = 0; ni < 4; ni++) {
            const int d = wn * 32 + ni * 8 + t4 * 2;   // even: RoPE pair (d, d+1) in-thread
            const int i = d >> 1;
            #pragma unroll
            for (int hl = 0; hl < 2; hl++) {
                const int s = sbase + wm * 64 + mi * 16 + g + hl * 8;
                float v0 = acc[mi][ni][hl * 2 + 0];
                float v1 = acc[mi][ni][hl * 2 + 1];
                if (rope) {
                    const float cs = __ldg(cosT + (size_t)s * 64 + i);
                    const float sn = __ldg(sinT + (size_t)s * 64 + i);
                    const float r0 = v0 * cs - v1 * sn;
                    const float r1 = v0 * sn + v1 * cs;
                    v0 = r0; v1 = r1;
                }
                float2 vv; vv.x = v0; vv.y = v1;
                __stcs(reinterpret_cast<float2*>(ob + (size_t)s * HD + d), vv);
            }
        }
    }
}

// ---------------- host ----------------
extern "C" void kernel_launch(void* const* d_in, const int* in_sizes, int n_in,
                              void* d_out, int out_size)
{
    const float* x    = (const float*)d_in[0];
    const float* wq   = (const float*)d_in[1];
    const float* wk   = (const float*)d_in[2];
    const float* wv   = (const float*)d_in[3];
    const float* cosT = (const float*)d_in[4];
    const float* sinT = (const float*)d_in[5];
    float* out = (float*)d_out;

    void *xh = nullptr, *wh = nullptr;
    cudaGetSymbolAddress(&xh, g_xh);
    cudaGetSymbolAddress(&wh, g_wh);

    // pre-pass: fp16 copies. grid = n4/1024 (exact for all tensors).
    cvt_f16_kernel<<<(MTOT * DIM / 4) / 1024, 256>>>((const uint4*)x, (uint4*)xh);
    cvt_f16_kernel<<<(NHEADS * HD * DIM / 4) / 1024, 256>>>((const uint4*)wq, (uint4*)wh);
    cvt_f16_kernel<<<(NKV * HD * DIM / 4) / 1024, 256>>>(
        (const uint4*)wk, (uint4*)((__half*)wh + (size_t)NHEADS * HD * DIM));
    cvt_f16_kernel<<<(NKV * HD * DIM / 4) / 1024, 256>>>(
        (const uint4*)wv, (uint4*)((__half*)wh + (size_t)(NHEADS + NKV) * HD * DIM));

    cudaFuncSetAttribute(qkv_hmma_f16_kernel,
                         cudaFuncAttributeMaxDynamicSharedMemorySize, SMEM_BYTES);

    const int grid = (MTOT / TM) * (NTOT / TN);   // 128 * 48 = 6144
    qkv_hmma_f16_kernel<<<grid, THREADS, SMEM_BYTES>>>(
        (const __half*)xh, (const __half*)wh, cosT, sinT, out);
}